// round 1
// baseline (speedup 1.0000x reference)
#include <cuda_runtime.h>
#include <cstdint>

#define TILE_M   128
#define LDA      132          // 128 + 4 floats pad -> conflict-free fragment LDS
#define NTHREADS 256

__device__ int g_idx_is64;

// Index dtype sniffing: int64 indices (< 2^31, non-negative) have all-zero high
// words; int32 index data at odd word positions is ~never all-zero for 64 samples.
__global__ void detect_idx_kernel(const unsigned int* __restrict__ w) {
    if (threadIdx.x == 0) {
        int is64 = 1;
        for (int i = 0; i < 64; i++)
            if (w[2 * i + 1] != 0u) { is64 = 0; break; }
        g_idx_is64 = is64;
    }
}

__device__ __forceinline__ void cp16(float* dst, const float* src) {
    uint32_t d = (uint32_t)__cvta_generic_to_shared(dst);
    asm volatile("cp.async.cg.shared.global [%0], [%1], 16;\n" :: "r"(d), "l"(src));
}

__device__ __forceinline__ uint32_t f2tf32(float v) {
    uint32_t u;
    asm("cvt.rna.tf32.f32 %0, %1;" : "=r"(u) : "f"(v));
    return u;
}

__global__ void __launch_bounds__(NTHREADS, 1)
edge_encoder_kernel(const float* __restrict__ x,
                    const float* __restrict__ ea,
                    const void* __restrict__ idx,
                    const float* __restrict__ Wg,
                    const float* __restrict__ bg,
                    float* __restrict__ out,
                    int E, int ntiles) {
    extern __shared__ float smem[];
    float* As = smem;                       // 2 stages * 128 * LDA
    float* Ws = smem + 2 * TILE_M * LDA;    // 128 * LDA  (TF32-rounded W)
    float* Bs = Ws + 128 * LDA;             // 128 bias

    const int tid  = threadIdx.x;
    const int lane = tid & 31;
    const int warp = tid >> 5;
    const int g    = lane >> 2;   // groupID 0..7
    const int tig  = lane & 3;    // thread-in-group 0..3
    const int wm   = warp >> 1;   // 0..3  (M)
    const int wn   = warp & 1;    // 0..1  (N)
    const int is64 = g_idx_is64;

    // Stage W (pre-rounded to TF32) and bias once per CTA.
    for (int i = tid; i < 128 * 128; i += NTHREADS) {
        int r = i >> 7, c = i & 127;
        Ws[r * LDA + c] = __uint_as_float(f2tf32(Wg[i]));
    }
    if (tid < 128) Bs[tid] = bg[tid];

    // Gather issue: thread owns one (row, half). half==0 -> x[row[e]], half==1 -> edge_attr[e].
    const int rowi = tid >> 1;
    const int half = tid & 1;

    auto issue = [&](int stage, long tile) {
        long e  = tile * TILE_M + rowi;
        long ec = e < E ? e : (long)(E - 1);
        const float* src;
        if (half == 0) {
            long r = is64 ? (long)((const long long*)idx)[ec]
                          : (long)((const int*)idx)[ec];
            src = x + (r << 6);
        } else {
            src = ea + (ec << 6);
        }
        float* dst = As + stage * (TILE_M * LDA) + rowi * LDA + half * 64;
        #pragma unroll
        for (int q = 0; q < 16; q++) cp16(dst + q * 4, src + q * 4);
    };

    long tile0 = blockIdx.x;
    if (tile0 < ntiles) issue(0, tile0);
    asm volatile("cp.async.commit_group;\n");
    __syncthreads();  // Ws / Bs visible to all warps

    float2 bb[8];
    #pragma unroll
    for (int nn = 0; nn < 8; nn++) {
        int col = wn * 64 + nn * 8 + 2 * tig;
        bb[nn] = make_float2(Bs[col], Bs[col + 1]);
    }

    int s = 0;
    for (long tile = tile0; tile < ntiles; tile += gridDim.x, s ^= 1) {
        long nxt = tile + gridDim.x;
        if (nxt < ntiles) issue(s ^ 1, nxt);
        asm volatile("cp.async.commit_group;\n");
        asm volatile("cp.async.wait_group 1;\n");   // current stage done, next in flight
        __syncthreads();

        const float* A0 = As + s * (TILE_M * LDA);

        float c[2][8][4];
        #pragma unroll
        for (int ms = 0; ms < 2; ms++)
            #pragma unroll
            for (int nn = 0; nn < 8; nn++)
                #pragma unroll
                for (int q = 0; q < 4; q++) c[ms][nn][q] = 0.f;

        const float* Ap = A0 + (wm * 32 + g) * LDA;
        const float* Bp = Ws + (wn * 64 + g) * LDA;

        #pragma unroll
        for (int k = 0; k < 128; k += 8) {
            uint32_t a[2][4];
            #pragma unroll
            for (int ms = 0; ms < 2; ms++) {
                const float* ap = Ap + ms * 16 * LDA + k + tig;
                a[ms][0] = f2tf32(ap[0]);
                a[ms][1] = f2tf32(ap[8 * LDA]);
                a[ms][2] = f2tf32(ap[4]);
                a[ms][3] = f2tf32(ap[8 * LDA + 4]);
            }
            uint32_t b[8][2];
            #pragma unroll
            for (int nn = 0; nn < 8; nn++) {
                const float* bp = Bp + nn * 8 * LDA + k + tig;
                b[nn][0] = __float_as_uint(bp[0]);
                b[nn][1] = __float_as_uint(bp[4]);
            }
            #pragma unroll
            for (int ms = 0; ms < 2; ms++)
                #pragma unroll
                for (int nn = 0; nn < 8; nn++) {
                    asm volatile(
                        "mma.sync.aligned.m16n8k8.row.col.f32.tf32.tf32.f32 "
                        "{%0,%1,%2,%3}, {%4,%5,%6,%7}, {%8,%9}, {%0,%1,%2,%3};\n"
                        : "+f"(c[ms][nn][0]), "+f"(c[ms][nn][1]),
                          "+f"(c[ms][nn][2]), "+f"(c[ms][nn][3])
                        : "r"(a[ms][0]), "r"(a[ms][1]), "r"(a[ms][2]), "r"(a[ms][3]),
                          "r"(b[nn][0]), "r"(b[nn][1]));
                }
        }

        // Epilogue: bias + relu + float2 stores (covers every output element).
        #pragma unroll
        for (int ms = 0; ms < 2; ms++) {
            long e0 = tile * TILE_M + wm * 32 + ms * 16 + g;
            #pragma unroll
            for (int hh = 0; hh < 2; hh++) {
                long e = e0 + hh * 8;
                if (e < E) {
                    float* orow = out + e * 128 + wn * 64 + 2 * tig;
                    #pragma unroll
                    for (int nn = 0; nn < 8; nn++) {
                        float v0 = fmaxf(c[ms][nn][2 * hh + 0] + bb[nn].x, 0.f);
                        float v1 = fmaxf(c[ms][nn][2 * hh + 1] + bb[nn].y, 0.f);
                        *(float2*)(orow + nn * 8) = make_float2(v0, v1);
                    }
                }
            }
        }
        __syncthreads();  // protect stage s before it is refilled next iteration
    }
}

extern "C" void kernel_launch(void* const* d_in, const int* in_sizes, int n_in,
                              void* d_out, int out_size) {
    const float* x  = (const float*)d_in[0];
    const float* ea = (const float*)d_in[1];
    const void*  idx = d_in[2];
    const float* W  = (const float*)d_in[3];
    const float* b  = (const float*)d_in[4];
    float* out = (float*)d_out;

    int E = in_sizes[1] / 64;                       // edge_attr is [E, 64]
    int ntiles = (E + TILE_M - 1) / TILE_M;

    int dev = 0, sms = 148;
    cudaGetDevice(&dev);
    cudaDeviceGetAttribute(&sms, cudaDevAttrMultiProcessorCount, dev);

    size_t smem = (size_t)(2 * TILE_M * LDA + 128 * LDA + 128) * sizeof(float);
    cudaFuncSetAttribute(edge_encoder_kernel,
                         cudaFuncAttributeMaxDynamicSharedMemorySize, (int)smem);

    detect_idx_kernel<<<1, 32>>>((const unsigned int*)idx);

    int grid = sms < ntiles ? sms : ntiles;
    edge_encoder_kernel<<<grid, NTHREADS, smem>>>(x, ea, idx, W, b, out, E, ntiles);
}